// round 10
// baseline (speedup 1.0000x reference)
#include <cuda_runtime.h>
#include <math.h>

// x [256, 64, 2048] fp32.
//   xm   = max(x, axis=1); gate = softmax(xm, -1)   (SSA groups=1 == identity)
//   out  = gate[:, None, :] * x
//
// R10: software-pipelined batch decoupling. CTA i:
//   phase A: col-max of unit i -> g_xm, arrive; 8th arriver of a batch runs
//            that row's softmax and raises its flag.
//   phase C: scale unit i-128 (16 batches older -> gate virtually always
//            ready; spin is a no-op). No same-batch wait => read and write
//            streams overlap continuously instead of lull/burst.
// Extra 128 tail CTAs run only phase C of the last 128 units. Dependency
// chain strictly descends in block index -> deadlock-free.

#define B  256
#define H  64
#define N  2048
#define TILE 256
#define UNITS (B * (N / TILE))   // 2048
#define DELAY 128                // units of pipeline delay (16 batches)
#define GRID (UNITS + DELAY)     // 2176

__device__ float g_xm[B * N];            // xm, overwritten in place with gate
__device__ int g_done[B];
__device__ volatile int g_flag[B];

__global__ void zero_kernel() {
    const int t = threadIdx.x;
    if (t < B) { g_done[t] = 0; g_flag[t] = 0; }
}

__global__ __launch_bounds__(256)
void fused_pipelined_kernel(const float* __restrict__ x, float* __restrict__ out) {
    __shared__ float pmax[4 * TILE];
    __shared__ float sred[8];
    __shared__ float s_scalar;
    __shared__ int   s_last;

    const int i    = blockIdx.x;
    const int t    = threadIdx.x;
    const int lane = t & 31;
    const int wid  = t >> 5;

    const int col4 = (t & 63) * 4;       // 0..252
    const int h0   = t >> 6;             // 0..3

    // ================= Phase A: col-max of unit i =================
    if (i < UNITS) {
        const int b  = i >> 3;
        const int c0 = (i & 7) * TILE;
        const float* xb = x + (size_t)b * (H * N) + c0;

        float4 pm = make_float4(-INFINITY, -INFINITY, -INFINITY, -INFINITY);
        #pragma unroll
        for (int j = 0; j < 16; ++j) {
            const int h = h0 + j * 4;
            float4 v = *reinterpret_cast<const float4*>(xb + (size_t)h * N + col4);
            pm.x = fmaxf(pm.x, v.x);
            pm.y = fmaxf(pm.y, v.y);
            pm.z = fmaxf(pm.z, v.z);
            pm.w = fmaxf(pm.w, v.w);
        }
        *reinterpret_cast<float4*>(pmax + h0 * TILE + col4) = pm;
        __syncthreads();

        {
            float m = fmaxf(fmaxf(pmax[0 * TILE + t], pmax[1 * TILE + t]),
                            fmaxf(pmax[2 * TILE + t], pmax[3 * TILE + t]));
            g_xm[(size_t)b * N + c0 + t] = m;
        }
        __syncthreads();

        if (t == 0) {
            __threadfence();
            s_last = (atomicAdd(&g_done[b], 1) == 7);
        }
        __syncthreads();

        if (s_last) {
            // softmax over g_xm[b, :]
            float* row = g_xm + (size_t)b * N;
            float4 v0 = __ldcg(reinterpret_cast<const float4*>(row + t * 8));
            float4 v1 = __ldcg(reinterpret_cast<const float4*>(row + t * 8 + 4));

            float tm = fmaxf(fmaxf(fmaxf(v0.x, v0.y), fmaxf(v0.z, v0.w)),
                             fmaxf(fmaxf(v1.x, v1.y), fmaxf(v1.z, v1.w)));
            #pragma unroll
            for (int o = 16; o > 0; o >>= 1)
                tm = fmaxf(tm, __shfl_xor_sync(0xffffffffu, tm, o));
            if (lane == 0) sred[wid] = tm;
            __syncthreads();
            if (wid == 0) {
                float m = (lane < 8) ? sred[lane] : -INFINITY;
                #pragma unroll
                for (int o = 4; o > 0; o >>= 1)
                    m = fmaxf(m, __shfl_xor_sync(0xffffffffu, m, o));
                if (lane == 0) s_scalar = m;
            }
            __syncthreads();
            const float gmax = s_scalar;
            __syncthreads();

            float4 e0, e1;
            e0.x = expf(v0.x - gmax); e0.y = expf(v0.y - gmax);
            e0.z = expf(v0.z - gmax); e0.w = expf(v0.w - gmax);
            e1.x = expf(v1.x - gmax); e1.y = expf(v1.y - gmax);
            e1.z = expf(v1.z - gmax); e1.w = expf(v1.w - gmax);
            float ts = ((e0.x + e0.y) + (e0.z + e0.w)) + ((e1.x + e1.y) + (e1.z + e1.w));
            #pragma unroll
            for (int o = 16; o > 0; o >>= 1)
                ts += __shfl_xor_sync(0xffffffffu, ts, o);
            if (lane == 0) sred[wid] = ts;
            __syncthreads();
            if (wid == 0) {
                float m = (lane < 8) ? sred[lane] : 0.0f;
                #pragma unroll
                for (int o = 4; o > 0; o >>= 1)
                    m += __shfl_xor_sync(0xffffffffu, m, o);
                if (lane == 0) s_scalar = m;
            }
            __syncthreads();
            const float inv = 1.0f / s_scalar;

            e0.x *= inv; e0.y *= inv; e0.z *= inv; e0.w *= inv;
            e1.x *= inv; e1.y *= inv; e1.z *= inv; e1.w *= inv;
            *reinterpret_cast<float4*>(row + t * 8)     = e0;
            *reinterpret_cast<float4*>(row + t * 8 + 4) = e1;
            __syncthreads();
            if (t == 0) {
                __threadfence();
                g_flag[b] = 1;
            }
        }
    }

    // ================= Phase C: scale unit i - DELAY =================
    if (i >= DELAY) {
        const int u  = i - DELAY;
        const int b  = u >> 3;
        const int c0 = (u & 7) * TILE;
        const float* xb = x   + (size_t)b * (H * N) + c0;
        float*       ob = out + (size_t)b * (H * N) + c0;

        if (t == 0) {
            while (g_flag[b] == 0) __nanosleep(100);
            __threadfence();
        }
        __syncthreads();

        const float4 g4 = __ldcg(reinterpret_cast<const float4*>(
                             g_xm + (size_t)b * N + c0 + col4));
        #pragma unroll
        for (int j = 0; j < 16; ++j) {
            const int h = h0 + j * 4;
            float4 v = __ldcs(reinterpret_cast<const float4*>(xb + (size_t)h * N + col4));
            v.x *= g4.x; v.y *= g4.y; v.z *= g4.z; v.w *= g4.w;
            __stcs(reinterpret_cast<float4*>(ob + (size_t)h * N + col4), v);
        }
    }
}

extern "C" void kernel_launch(void* const* d_in, const int* in_sizes, int n_in,
                              void* d_out, int out_size) {
    const float* x = (const float*)d_in[0];
    float* out = (float*)d_out;

    zero_kernel<<<1, 256>>>();
    fused_pipelined_kernel<<<GRID, 256>>>(x, out);
}

// round 11
// speedup vs baseline: 1.0503x; 1.0503x over previous
#include <cuda_runtime.h>
#include <math.h>

// x [256, 64, 2048] fp32.
//   xm   = max(x, axis=1); gate = softmax(xm, -1)   (SSA groups=1 == identity)
//   out  = gate[:, None, :] * x
//
// R11: distributed split-softmax. 2048 CTAs x 256 thr, CTA u owns unit
// [64 x 256] (b = u>>3). Phase A: col-max (xm_t per thread). Local reduce ->
// (m_u, s_u) pair, publish 8 bytes, bump done[b]. All 8 batch CTAs arrive
// ~simultaneously (identical work, co-resident); each reads the 8 pairs and
// combines M, S, then computes its own 256 gates locally. Phase C: re-read
// unit (short reuse distance -> L2), scale, __stcs. No serial softmax, no
// g_xm global round-trip.

#define B  256
#define H  64
#define N  2048
#define TILE 256
#define UNITS (B * (N / TILE))   // 2048

__device__ float2 g_pair[UNITS];     // (local max, local expsum) per unit
__device__ int    g_done[B];

__global__ void zero_kernel() {
    const int t = threadIdx.x;
    if (t < B) g_done[t] = 0;
}

__global__ __launch_bounds__(256)
void fused_splitsoftmax_kernel(const float* __restrict__ x, float* __restrict__ out) {
    __shared__ float pmax[4 * TILE];     // 4 KB
    __shared__ float gate_s[TILE];       // 1 KB
    __shared__ float sred[8];
    __shared__ float s_m, s_s;

    const int u  = blockIdx.x;
    const int b  = u >> 3;
    const int c0 = (u & 7) * TILE;
    const int t    = threadIdx.x;
    const int lane = t & 31;
    const int wid  = t >> 5;             // 8 warps

    const float* xb = x   + (size_t)b * (H * N) + c0;
    float*       ob = out + (size_t)b * (H * N) + c0;

    const int col4 = (t & 63) * 4;       // 0..252
    const int h0   = t >> 6;             // 0..3

    // ---------------- Phase A: column max over 64 rows ----------------
    float4 pm = make_float4(-INFINITY, -INFINITY, -INFINITY, -INFINITY);
    #pragma unroll
    for (int j = 0; j < 16; ++j) {
        const int h = h0 + j * 4;
        float4 v = *reinterpret_cast<const float4*>(xb + (size_t)h * N + col4);
        pm.x = fmaxf(pm.x, v.x);
        pm.y = fmaxf(pm.y, v.y);
        pm.z = fmaxf(pm.z, v.z);
        pm.w = fmaxf(pm.w, v.w);
    }
    *reinterpret_cast<float4*>(pmax + h0 * TILE + col4) = pm;
    __syncthreads();

    // thread t owns column t: xm_t
    const float xm_t = fmaxf(fmaxf(pmax[0 * TILE + t], pmax[1 * TILE + t]),
                             fmaxf(pmax[2 * TILE + t], pmax[3 * TILE + t]));

    // ---------------- local (m_u, s_u) ----------------
    float m = xm_t;
    #pragma unroll
    for (int o = 16; o > 0; o >>= 1)
        m = fmaxf(m, __shfl_xor_sync(0xffffffffu, m, o));
    if (lane == 0) sred[wid] = m;
    __syncthreads();
    if (wid == 0) {
        float v = (lane < 8) ? sred[lane] : -INFINITY;
        #pragma unroll
        for (int o = 4; o > 0; o >>= 1)
            v = fmaxf(v, __shfl_xor_sync(0xffffffffu, v, o));
        if (lane == 0) s_m = v;
    }
    __syncthreads();
    const float m_u = s_m;

    const float e_t = expf(xm_t - m_u);
    float s = e_t;
    #pragma unroll
    for (int o = 16; o > 0; o >>= 1)
        s += __shfl_xor_sync(0xffffffffu, s, o);
    if (lane == 0) sred[wid] = s;
    __syncthreads();
    if (wid == 0) {
        float v = (lane < 8) ? sred[lane] : 0.0f;
        #pragma unroll
        for (int o = 4; o > 0; o >>= 1)
            v += __shfl_xor_sync(0xffffffffu, v, o);
        if (lane == 0) s_s = v;
    }
    __syncthreads();

    // ---------------- publish pair, arrive ----------------
    if (t == 0) {
        g_pair[u] = make_float2(m_u, s_s);
        __threadfence();
        atomicAdd(&g_done[b], 1);
        // spin until all 8 pairs of this batch are published
        while (atomicAdd(&g_done[b], 0) < 8) { }
        __threadfence();
    }
    __syncthreads();

    // ---------------- combine 8 pairs -> M, S (redundant per thread) -------
    float M = -INFINITY;
    float2 pr[8];
    #pragma unroll
    for (int j = 0; j < 8; ++j) {
        const float2* pp = &g_pair[(b << 3) + j];
        float2 p;
        p.x = __ldcg(&pp->x);
        p.y = __ldcg(&pp->y);
        pr[j] = p;
        M = fmaxf(M, p.x);
    }
    float S = 0.0f;
    #pragma unroll
    for (int j = 0; j < 8; ++j)
        S += pr[j].y * expf(pr[j].x - M);
    const float invS = 1.0f / S;

    // this thread's gate: exp(xm_t - M)/S = e_t * exp(m_u - M) / S
    gate_s[t] = e_t * expf(m_u - M) * invS;
    __syncthreads();

    // ---------------- Phase C: out = gate * x ----------------
    const float4 g4 = *reinterpret_cast<const float4*>(gate_s + col4);
    #pragma unroll
    for (int j = 0; j < 16; ++j) {
        const int h = h0 + j * 4;
        float4 v = __ldcs(reinterpret_cast<const float4*>(xb + (size_t)h * N + col4));
        v.x *= g4.x; v.y *= g4.y; v.z *= g4.z; v.w *= g4.w;
        __stcs(reinterpret_cast<float4*>(ob + (size_t)h * N + col4), v);
    }
}

extern "C" void kernel_launch(void* const* d_in, const int* in_sizes, int n_in,
                              void* d_out, int out_size) {
    const float* x = (const float*)d_in[0];
    float* out = (float*)d_out;

    zero_kernel<<<1, 256>>>();
    fused_splitsoftmax_kernel<<<UNITS, 256>>>(x, out);
}